// round 5
// baseline (speedup 1.0000x reference)
#include <cuda_runtime.h>

// GaussianBlur: depthwise 21x21 Gaussian (sigma=5), reflect pad 10,
// input/output [32, 3, 512, 512] fp32 -> treat as 96 independent 512x512 images.
// Separable: out = colconv(rowconv(x)). Weights are the normalized 1D Gaussian
// (2D kernel = outer(g1,g1)/sum => each 1D pass uses g1/sqrt(sum2) == g1/S).

#define W_ 512
#define H_ 512
#define NIMG 96
#define PAD 10
#define ROWW (W_ + 2 * PAD)   // 532

// 1D separable weights: exp(-(d^2)/50) / 12.089199128, d = |k-10|
__device__ __constant__ const float KW[21] = {
    0.01119473f, 0.01636989f, 0.02299883f, 0.03104516f, 0.04026340f,
    0.05017128f, 0.06006594f, 0.06909227f, 0.07635877f, 0.08108053f,
    0.08271847f,
    0.08108053f, 0.07635877f, 0.06909227f, 0.06006594f, 0.05017128f,
    0.04026340f, 0.03104516f, 0.02299883f, 0.01636989f, 0.01119473f
};

// Scratch for the horizontal-pass result (96*512*512 floats = 100.7 MB).
// __device__ global: allocation-free per harness rules.
__device__ float g_scratch[NIMG * H_ * W_];

__device__ __forceinline__ int reflect512(int i) {
    // jnp.pad mode="reflect": -k -> k, 511+k -> 511-k (single reflection, PAD<512)
    i = (i < 0) ? -i : i;
    return (i > 511) ? (1022 - i) : i;
}

// ---------------------------------------------------------------------------
// Pass 1: horizontal 21-tap. Block (128, 2): 2 rows per iteration, 16 iters
// per block => 32 rows/block. Each thread computes 4 adjacent x outputs from
// an aligned 24-float smem window (6x LDS.128, conflict-free phases).
// ---------------------------------------------------------------------------
__global__ __launch_bounds__(256) void hpass_kernel(const float* __restrict__ in) {
    __shared__ __align__(16) float srow[2][544];  // 532 used, padded stride

    const int n  = blockIdx.y;                 // image (b*c)
    const int rb = blockIdx.x * 32;            // first row of this block
    const int tx = threadIdx.x;                // 0..127
    const int ty = threadIdx.y;                // 0..1

    const float* __restrict__ inp = in + (size_t)n * H_ * W_;
    float* __restrict__ outp = g_scratch + (size_t)n * H_ * W_;

    for (int it = 0; it < 16; ++it) {
        const int row = rb + it * 2 + ty;
        const float* __restrict__ rin = inp + (size_t)row * W_;

        // Coalesced load of the padded row (reflect at x borders).
        #pragma unroll
        for (int i = tx; i < ROWW; i += 128) {
            srow[ty][i] = rin[reflect512(i - PAD)];
        }
        __syncthreads();

        // Aligned 24-float window: outputs [4tx..4tx+3] need in[4tx-10..4tx+13],
        // stored at srow offsets [4tx..4tx+23].
        const float* s = srow[ty] + 4 * tx;
        float v[24];
        #pragma unroll
        for (int j = 0; j < 6; ++j) {
            float4 t = *reinterpret_cast<const float4*>(s + 4 * j);
            v[4 * j + 0] = t.x; v[4 * j + 1] = t.y;
            v[4 * j + 2] = t.z; v[4 * j + 3] = t.w;
        }

        float a0 = 0.f, a1 = 0.f, a2 = 0.f, a3 = 0.f;
        #pragma unroll
        for (int k = 0; k < 21; ++k) {
            const float w = KW[k];
            a0 = fmaf(w, v[k + 0], a0);
            a1 = fmaf(w, v[k + 1], a1);
            a2 = fmaf(w, v[k + 2], a2);
            a3 = fmaf(w, v[k + 3], a3);
        }
        *reinterpret_cast<float4*>(outp + (size_t)row * W_ + 4 * tx) =
            make_float4(a0, a1, a2, a3);
        __syncthreads();  // protect srow before next iteration's load
    }
}

// ---------------------------------------------------------------------------
// Pass 2: vertical 21-tap. No smem: each thread owns one column x and a strip
// of 32 consecutive y. Loads a 52-row register window (coalesced across the
// warp, all 52 loads front-batched -> high MLP), computes 32 outputs.
// ---------------------------------------------------------------------------
__global__ __launch_bounds__(256) void vpass_kernel(float* __restrict__ out) {
    const int n  = blockIdx.z;
    const int x  = blockIdx.x * 256 + threadIdx.x;    // 0..511
    const int y0 = blockIdx.y * 32;                    // strip start

    const float* __restrict__ inp = g_scratch + (size_t)n * H_ * W_ + x;
    float* __restrict__ outp = out + (size_t)n * H_ * W_ + x;

    float v[52];
    #pragma unroll
    for (int j = 0; j < 52; ++j) {
        const int gy = reflect512(y0 - PAD + j);
        v[j] = inp[(size_t)gy * W_];
    }

    #pragma unroll
    for (int r = 0; r < 32; ++r) {
        float a = 0.f;
        #pragma unroll
        for (int k = 0; k < 21; ++k) {
            a = fmaf(KW[k], v[r + k], a);
        }
        outp[(size_t)(y0 + r) * W_] = a;
    }
}

extern "C" void kernel_launch(void* const* d_in, const int* in_sizes, int n_in,
                              void* d_out, int out_size) {
    const float* x = (const float*)d_in[0];
    float* out = (float*)d_out;
    (void)in_sizes; (void)n_in; (void)out_size;

    // Pass 1: grid (16 row-chunks, 96 images), block (128, 2)
    hpass_kernel<<<dim3(16, NIMG), dim3(128, 2)>>>(x);
    // Pass 2: grid (2 x-chunks, 16 y-strips, 96 images), block 256
    vpass_kernel<<<dim3(2, 16, NIMG), 256>>>(out);
}